// round 1
// baseline (speedup 1.0000x reference)
#include <cuda_runtime.h>

#define BATCH 2
#define N1 8192
#define CIN 128

// ---------------- scratch (device globals; no allocations allowed) ----------
// cv pyramid stored TRANSPOSED: cvT[b][m][n1]  (m = level point idx, n1 contiguous)
static __device__ float g_cv0[134217728];   // [2][8192][8192]  512 MB
static __device__ float g_cv1[33554432];    // [2][2048][8192]  128 MB
static __device__ float g_cv2[8388608];     // [2][ 512][8192]   32 MB
static __device__ float g_cv3[2097152];     // [2][ 128][8192]    8 MB
// indices: cross-knn (4 levels x 2*8192*16) then pyramid knn (k=3)
#define IDX_CROSS_STRIDE 262144            // 2*8192*16
#define IDX_PYR_BASE     1048576           // 4*262144
#define IDX_PYR1         (IDX_PYR_BASE)           // 2*2048*3 = 12288
#define IDX_PYR2         (IDX_PYR_BASE + 12288)   // 2*512*3  = 3072
#define IDX_PYR3         (IDX_PYR_BASE + 15360)   // 2*128*3  = 768
static __device__ int   g_idx[1048576 + 16128];
static __device__ float g_costs[1048576];   // [2][64][8192]

__device__ __forceinline__ float* cv_ptr(int lvl) {
    switch (lvl) {
        case 0: return g_cv0;
        case 1: return g_cv1;
        case 2: return g_cv2;
        default: return g_cv3;
    }
}

// ---------------- kernel 1: cost volume GEMM --------------------------------
// cvT[b][m][n] = (1/128) * sum_c feat2[b][c][m] * feat1[b][c][n]
// feat layout: [B][128][8192] row-major -> rows contiguous in point index.
__global__ void __launch_bounds__(256) gemm_cv(const float* __restrict__ feat1,
                                               const float* __restrict__ feat2)
{
    __shared__ float As[8][128];   // feat2 tile: [k][m]
    __shared__ float Bs[8][128];   // feat1 tile: [k][n]
    const int b  = blockIdx.z;
    const int m0 = blockIdx.y * 128;
    const int n0 = blockIdx.x * 128;
    const float* A  = feat2 + (size_t)b * CIN * 8192;
    const float* Bp = feat1 + (size_t)b * CIN * 8192;
    const int tid = threadIdx.x;
    const int tm = (tid >> 4) * 8;
    const int tn = (tid & 15) * 8;

    float acc[8][8];
#pragma unroll
    for (int i = 0; i < 8; i++)
#pragma unroll
        for (int j = 0; j < 8; j++) acc[i][j] = 0.0f;

    for (int k0 = 0; k0 < CIN; k0 += 8) {
#pragma unroll
        for (int i = 0; i < 4; i++) {
            int idx = tid + i * 256;
            int kk = idx >> 7;
            int mm = idx & 127;
            As[kk][mm] = A [(size_t)(k0 + kk) * 8192 + m0 + mm];
            Bs[kk][mm] = Bp[(size_t)(k0 + kk) * 8192 + n0 + mm];
        }
        __syncthreads();
#pragma unroll
        for (int kk = 0; kk < 8; kk++) {
            float a[8], bb[8];
#pragma unroll
            for (int i = 0; i < 8; i++) a[i]  = As[kk][tm + i];
#pragma unroll
            for (int j = 0; j < 8; j++) bb[j] = Bs[kk][tn + j];
#pragma unroll
            for (int i = 0; i < 8; i++)
#pragma unroll
                for (int j = 0; j < 8; j++)
                    acc[i][j] = fmaf(a[i], bb[j], acc[i][j]);
        }
        __syncthreads();
    }

    float* out = g_cv0 + (size_t)b * 8192 * 8192;
#pragma unroll
    for (int i = 0; i < 8; i++) {
        size_t row = (size_t)(m0 + tm + i) * 8192 + (n0 + tn);
#pragma unroll
        for (int j = 0; j < 8; j++)
            out[row + j] = acc[i][j] * 0.0078125f;
    }
}

// ---------------- kernel 2: brute-force KNN ---------------------------------
// One thread per query point; candidate points staged through smem in chunks.
// Distance formula mirrors reference: q2 + i2 - 2*dot. Set-equality with
// jax top_k is all we need (downstream ops are permutation-invariant in k).
template <int K>
__global__ void __launch_bounds__(128) knn_kernel(const float* __restrict__ qxyz,
                                                  const float* __restrict__ pxyz,
                                                  int Nq, int Ni, int out_off)
{
    const int CH = 1024;
    __shared__ float sx[CH], sy[CH], sz[CH];
    const int b  = blockIdx.y;
    const int qi = blockIdx.x * 128 + threadIdx.x;

    const float qx = qxyz[(size_t)(b * 3 + 0) * Nq + qi];
    const float qy = qxyz[(size_t)(b * 3 + 1) * Nq + qi];
    const float qz = qxyz[(size_t)(b * 3 + 2) * Nq + qi];
    const float qq = qx * qx + qy * qy + qz * qz;

    float bd[K];
    int   bi[K];
#pragma unroll
    for (int j = 0; j < K; j++) { bd[j] = 1e30f; bi[j] = 0; }

    for (int c0 = 0; c0 < Ni; c0 += CH) {
        const int cnt = min(CH, Ni - c0);
        for (int t = threadIdx.x; t < cnt; t += 128) {
            sx[t] = pxyz[(size_t)(b * 3 + 0) * Ni + c0 + t];
            sy[t] = pxyz[(size_t)(b * 3 + 1) * Ni + c0 + t];
            sz[t] = pxyz[(size_t)(b * 3 + 2) * Ni + c0 + t];
        }
        __syncthreads();
        for (int t = 0; t < cnt; t++) {
            const float ix = sx[t], iy = sy[t], iz = sz[t];
            const float ii = ix * ix + iy * iy + iz * iz;
            const float d  = qq + ii - 2.0f * (qx * ix + qy * iy + qz * iz);
            if (d < bd[K - 1]) {                 // strict: earlier index wins ties
                bd[K - 1] = d; bi[K - 1] = c0 + t;
#pragma unroll
                for (int j = K - 1; j > 0; j--) {
                    if (bd[j] < bd[j - 1]) {
                        float td = bd[j]; bd[j] = bd[j - 1]; bd[j - 1] = td;
                        int   ti = bi[j]; bi[j] = bi[j - 1]; bi[j - 1] = ti;
                    }
                }
            }
        }
        __syncthreads();
    }

    int* out = g_idx + out_off;
#pragma unroll
    for (int j = 0; j < K; j++)
        out[((size_t)b * Nq + qi) * K + j] = bi[j];
}

// ---------------- kernel 3: pyramid k=3 average -----------------------------
// cvT_new[b][m][n] = mean_j cvT_prev[b][idx[b][m][j]][n]  — fully coalesced in n.
__global__ void __launch_bounds__(256) pyr_avg(int lvl, int Nm, int Nprev, int idx_off)
{
    const float* prev = cv_ptr(lvl - 1);
    float* out        = cv_ptr(lvl);
    const int b = blockIdx.z;
    const int m = blockIdx.y;
    const int n = blockIdx.x * 256 + threadIdx.x;
    const int* ip = g_idx + idx_off + ((size_t)b * Nm + m) * 3;
    const int i0 = ip[0], i1 = ip[1], i2 = ip[2];
    const float v = prev[((size_t)b * Nprev + i0) * 8192 + n]
                  + prev[((size_t)b * Nprev + i1) * 8192 + n]
                  + prev[((size_t)b * Nprev + i2) * 8192 + n];
    out[((size_t)b * Nm + m) * 8192 + n] = v * (1.0f / 3.0f);
}

// ---------------- kernel 4: per-level matching cost MLP ---------------------
// feat = [dx,dy,dz,corr]; h1 = relu(w1 f + b1); h2 = relu(w2 h1 + b2);
// costs[b][lvl*16+o][n] = sum_k h2[o]
__global__ void __launch_bounds__(128) level_cost(const float* __restrict__ xyz1,
                                                  const float* __restrict__ xyz2,
                                                  int lvl, int Nl,
                                                  const float* __restrict__ w1,
                                                  const float* __restrict__ b1,
                                                  const float* __restrict__ w2,
                                                  const float* __restrict__ b2)
{
    __shared__ float sw1[64], sb1[16], sw2[256], sb2[16];
    const int t = threadIdx.x;
    if (t < 64) sw1[t] = w1[t];
    if (t < 16) sb1[t] = b1[t];
    for (int i = t; i < 256; i += 128) sw2[i] = w2[i];
    if (t >= 64 && t < 80) sb2[t - 64] = b2[t - 64];
    __syncthreads();

    const int b = blockIdx.y;
    const int n = blockIdx.x * 128 + t;
    const float* cvT = cv_ptr(lvl);
    const int* ip = g_idx + (size_t)lvl * IDX_CROSS_STRIDE + ((size_t)b * N1 + n) * 16;

    const float px = xyz1[(size_t)(b * 3 + 0) * N1 + n];
    const float py = xyz1[(size_t)(b * 3 + 1) * N1 + n];
    const float pz = xyz1[(size_t)(b * 3 + 2) * N1 + n];

    float acc[16];
#pragma unroll
    for (int o = 0; o < 16; o++) acc[o] = 0.0f;

#pragma unroll 4
    for (int k = 0; k < 16; k++) {
        const int i = ip[k];
        const float dx = xyz2[(size_t)(b * 3 + 0) * Nl + i] - px;
        const float dy = xyz2[(size_t)(b * 3 + 1) * Nl + i] - py;
        const float dz = xyz2[(size_t)(b * 3 + 2) * Nl + i] - pz;
        const float corr = cvT[((size_t)b * Nl + i) * 8192 + n];

        float h1[16];
#pragma unroll
        for (int o = 0; o < 16; o++) {
            float a = fmaf(sw1[o * 4 + 0], dx, sb1[o]);
            a = fmaf(sw1[o * 4 + 1], dy, a);
            a = fmaf(sw1[o * 4 + 2], dz, a);
            a = fmaf(sw1[o * 4 + 3], corr, a);
            h1[o] = fmaxf(a, 0.0f);
        }
#pragma unroll
        for (int o2 = 0; o2 < 16; o2++) {
            float a = sb2[o2];
#pragma unroll
            for (int o = 0; o < 16; o++) a = fmaf(sw2[o2 * 16 + o], h1[o], a);
            acc[o2] += fmaxf(a, 0.0f);
        }
    }
#pragma unroll
    for (int o2 = 0; o2 < 16; o2++)
        g_costs[((size_t)b * 64 + lvl * 16 + o2) * N1 + n] = acc[o2];
}

// ---------------- kernel 5: final 64x64 MLP ---------------------------------
__global__ void __launch_bounds__(256) final_mlp(const float* __restrict__ wm,
                                                 const float* __restrict__ bm,
                                                 float* __restrict__ out)
{
    __shared__ float swm[4096];
    __shared__ float sbm[64];
    const int t = threadIdx.x;
    for (int i = t; i < 4096; i += 256) swm[i] = wm[i];
    if (t < 64) sbm[t] = bm[t];
    __syncthreads();

    const int b = blockIdx.y;
    const int n = blockIdx.x * 256 + t;

    float c[64];
#pragma unroll
    for (int cc = 0; cc < 64; cc++)
        c[cc] = g_costs[((size_t)b * 64 + cc) * N1 + n];

#pragma unroll 4
    for (int o = 0; o < 64; o++) {
        float a = sbm[o];
#pragma unroll
        for (int cc = 0; cc < 64; cc++)
            a = fmaf(swm[o * 64 + cc], c[cc], a);
        out[((size_t)b * 64 + o) * N1 + n] = fmaxf(a, 0.0f);
    }
}

// ---------------- launcher ---------------------------------------------------
extern "C" void kernel_launch(void* const* d_in, const int* in_sizes, int n_in,
                              void* d_out, int out_size)
{
    const float* xyz1   = (const float*)d_in[0];
    const float* xyz2_0 = (const float*)d_in[1];
    const float* xyz2_1 = (const float*)d_in[2];
    const float* xyz2_2 = (const float*)d_in[3];
    const float* xyz2_3 = (const float*)d_in[4];
    const float* feat1  = (const float*)d_in[5];
    const float* feat2  = (const float*)d_in[6];
    const float* w1 = (const float*)d_in[7];
    const float* b1 = (const float*)d_in[8];
    const float* w2 = (const float*)d_in[9];
    const float* b2 = (const float*)d_in[10];
    const float* wm = (const float*)d_in[11];
    const float* bm = (const float*)d_in[12];
    float* out = (float*)d_out;

    // 1) cost volume (transposed): cvT0[b][m][n1]
    gemm_cv<<<dim3(64, 64, 2), 256>>>(feat1, feat2);

    // 2) pyramid KNN (k=3): query = finer-level-(i) points, input = level-(i-1)
    knn_kernel<3><<<dim3(2048 / 128, 2), 128>>>(xyz2_1, xyz2_0, 2048, 8192, IDX_PYR1);
    knn_kernel<3><<<dim3( 512 / 128, 2), 128>>>(xyz2_2, xyz2_1,  512, 2048, IDX_PYR2);
    knn_kernel<3><<<dim3( 128 / 128, 2), 128>>>(xyz2_3, xyz2_2,  128,  512, IDX_PYR3);

    // 3) cross KNN (k=16): query = xyz1 at every level
    knn_kernel<16><<<dim3(64, 2), 128>>>(xyz1, xyz2_0, N1, 8192, 0 * IDX_CROSS_STRIDE);
    knn_kernel<16><<<dim3(64, 2), 128>>>(xyz1, xyz2_1, N1, 2048, 1 * IDX_CROSS_STRIDE);
    knn_kernel<16><<<dim3(64, 2), 128>>>(xyz1, xyz2_2, N1,  512, 2 * IDX_CROSS_STRIDE);
    knn_kernel<16><<<dim3(64, 2), 128>>>(xyz1, xyz2_3, N1,  128, 3 * IDX_CROSS_STRIDE);

    // 4) pyramid averaging (needs gemm + pyramid knn; stream order guarantees it)
    pyr_avg<<<dim3(32, 2048, 2), 256>>>(1, 2048, 8192, IDX_PYR1);
    pyr_avg<<<dim3(32,  512, 2), 256>>>(2,  512, 2048, IDX_PYR2);
    pyr_avg<<<dim3(32,  128, 2), 256>>>(3,  128,  512, IDX_PYR3);

    // 5) per-level matching cost MLPs
    level_cost<<<dim3(64, 2), 128>>>(xyz1, xyz2_0, 0, 8192, w1, b1, w2, b2);
    level_cost<<<dim3(64, 2), 128>>>(xyz1, xyz2_1, 1, 2048, w1, b1, w2, b2);
    level_cost<<<dim3(64, 2), 128>>>(xyz1, xyz2_2, 2,  512, w1, b1, w2, b2);
    level_cost<<<dim3(64, 2), 128>>>(xyz1, xyz2_3, 3,  128, w1, b1, w2, b2);

    // 6) final MLP -> output [2][64][8192]
    final_mlp<<<dim3(32, 2), 256>>>(wm, bm, out);
}

// round 2
// speedup vs baseline: 1.4672x; 1.4672x over previous
#include <cuda_runtime.h>
#include <cuda_bf16.h>
#include <cstdint>

#define BATCH 2
#define N1 8192
#define CIN 128

// ---------------- scratch (device globals; no allocations allowed) ----------
// cv pyramid stored TRANSPOSED: cvT[b][m][n1]  (m = level point idx, n1 contiguous)
static __device__ float g_cv0[134217728];   // [2][8192][8192]  512 MB
static __device__ float g_cv1[33554432];    // [2][2048][8192]  128 MB
static __device__ float g_cv2[8388608];     // [2][ 512][8192]   32 MB
static __device__ float g_cv3[2097152];     // [2][ 128][8192]    8 MB
// indices: cross-knn (4 levels x 2*8192*16) then pyramid knn (k=3)
#define IDX_CROSS_STRIDE 262144            // 2*8192*16
#define IDX_PYR_BASE     1048576           // 4*262144
#define IDX_PYR1         (IDX_PYR_BASE)           // 2*2048*3 = 12288
#define IDX_PYR2         (IDX_PYR_BASE + 12288)   // 2*512*3  = 3072
#define IDX_PYR3         (IDX_PYR_BASE + 15360)   // 2*128*3  = 768
static __device__ int   g_idx[1048576 + 16128];
static __device__ float g_costs[1048576];   // [2][64][8192]

// bf16 split operands for the tensor-core cost-volume GEMM
#define FEAT_ELEMS 2097152                 // 2*128*8192
static __device__ __nv_bfloat16 g_f1h[FEAT_ELEMS];
static __device__ __nv_bfloat16 g_f1l[FEAT_ELEMS];
static __device__ __nv_bfloat16 g_f2h[FEAT_ELEMS];   // scaled by 1/128
static __device__ __nv_bfloat16 g_f2l[FEAT_ELEMS];

__device__ __forceinline__ float* cv_ptr(int lvl) {
    switch (lvl) {
        case 0: return g_cv0;
        case 1: return g_cv1;
        case 2: return g_cv2;
        default: return g_cv3;
    }
}

// ---------------- kernel 0: bf16 hi/lo split ---------------------------------
__global__ void __launch_bounds__(256) split_bf16(const float* __restrict__ feat1,
                                                  const float* __restrict__ feat2)
{
    const int i = blockIdx.x * 256 + threadIdx.x;
    if (i >= FEAT_ELEMS) return;
    {
        float a = feat1[i];
        __nv_bfloat16 h = __float2bfloat16_rn(a);
        g_f1h[i] = h;
        g_f1l[i] = __float2bfloat16_rn(a - __bfloat162float(h));
    }
    {
        float a = feat2[i] * 0.0078125f;   // fold 1/128 here (exact pow2 scale)
        __nv_bfloat16 h = __float2bfloat16_rn(a);
        g_f2h[i] = h;
        g_f2l[i] = __float2bfloat16_rn(a - __bfloat162float(h));
    }
}

// ---------------- kernel 1: cost volume GEMM (bf16 split, mma.sync) ----------
// cvT[b][m][n] = sum_c f2s[c][m] * f1[c][n], f2s pre-scaled by 1/128.
// split: x = xh + xl; keep hh + hl + lh terms (drop ll, ~2^-18 relative).
#define BK 32
#define STAGE_ELEMS 4352          // 32 * 136 (pad 8 -> conflict-free ldmatrix)
// smem layout (bf16 elems): Ah[2 stages], Al, Bh, Bl
__device__ __forceinline__ void cp_async16(void* smem, const void* gmem) {
    unsigned saddr = (unsigned)__cvta_generic_to_shared(smem);
    asm volatile("cp.async.cg.shared.global [%0], [%1], 16;\n" :: "r"(saddr), "l"(gmem));
}
__device__ __forceinline__ void ldsm4t(uint32_t r[4], const __nv_bfloat16* p) {
    unsigned saddr = (unsigned)__cvta_generic_to_shared((void*)p);
    asm volatile("ldmatrix.sync.aligned.m8n8.x4.trans.shared.b16 {%0,%1,%2,%3}, [%4];"
                 : "=r"(r[0]), "=r"(r[1]), "=r"(r[2]), "=r"(r[3]) : "r"(saddr));
}
__device__ __forceinline__ void mma16816(float d[4], const uint32_t a[4], const uint32_t b[2]) {
    asm volatile("mma.sync.aligned.m16n8k16.row.col.f32.bf16.bf16.f32 "
                 "{%0,%1,%2,%3}, {%4,%5,%6,%7}, {%8,%9}, {%0,%1,%2,%3};"
                 : "+f"(d[0]), "+f"(d[1]), "+f"(d[2]), "+f"(d[3])
                 : "r"(a[0]), "r"(a[1]), "r"(a[2]), "r"(a[3]), "r"(b[0]), "r"(b[1]));
}

__global__ void __launch_bounds__(256) gemm_cv_mma()
{
    extern __shared__ __nv_bfloat16 sm[];
    __nv_bfloat16* sAh = sm;                    // [2][32][136]
    __nv_bfloat16* sAl = sm + 2 * STAGE_ELEMS;
    __nv_bfloat16* sBh = sm + 4 * STAGE_ELEMS;
    __nv_bfloat16* sBl = sm + 6 * STAGE_ELEMS;

    const int b  = blockIdx.z;
    const int m0 = blockIdx.y * 128;
    const int n0 = blockIdx.x * 128;
    const int tid  = threadIdx.x;
    const int lane = tid & 31;
    const int warp = tid >> 5;
    const int wm = (warp & 3) * 32;             // 4 warps along m
    const int wn = (warp >> 2) * 64;            // 2 warps along n

    // global sources for this CTA tile (bf16 element offsets)
    const __nv_bfloat16* gAh = g_f2h + (size_t)b * CIN * 8192 + m0;
    const __nv_bfloat16* gAl = g_f2l + (size_t)b * CIN * 8192 + m0;
    const __nv_bfloat16* gBh = g_f1h + (size_t)b * CIN * 8192 + n0;
    const __nv_bfloat16* gBl = g_f1l + (size_t)b * CIN * 8192 + n0;

    // per-thread load coords: 2 x 16B per array per stage
    const int l_row0 = tid >> 4;                // 0..15
    const int l_col0 = (tid & 15) * 8;          // 0..120
    // second vector: linear = tid + 256 -> row + 16
    // load helper macro
#define LOAD_STAGE(stg, k0)                                                          \
    {                                                                                \
        _Pragma("unroll")                                                            \
        for (int i = 0; i < 2; i++) {                                                \
            int row = l_row0 + i * 16;                                               \
            size_t gofs = (size_t)((k0) + row) * 8192 + l_col0;                      \
            int sofs = (stg) * STAGE_ELEMS + row * 136 + l_col0;                     \
            cp_async16(sAh + sofs, gAh + gofs);                                      \
            cp_async16(sAl + sofs, gAl + gofs);                                      \
            cp_async16(sBh + sofs, gBh + gofs);                                      \
            cp_async16(sBl + sofs, gBl + gofs);                                      \
        }                                                                            \
        asm volatile("cp.async.commit_group;\n" ::);                                 \
    }

    float acc[2][8][4];
#pragma unroll
    for (int mt = 0; mt < 2; mt++)
#pragma unroll
        for (int j = 0; j < 8; j++)
#pragma unroll
            for (int r = 0; r < 4; r++) acc[mt][j][r] = 0.0f;

    // ldmatrix per-lane offset patterns (bf16 element units, within a stage)
    // A (x4.trans): row = kb + (lane&7) + ((lane>>4)<<3); col = mbase + ((lane>>3)&1)*8
    const int a_row = (lane & 7) + ((lane >> 4) << 3);
    const int a_col = ((lane >> 3) & 1) * 8;
    // B (x4.trans, 2 n-tiles): row = kb + (lane&7) + ((lane>>3)&1)*8; col = nb + ((lane>>4)<<3)
    const int b_row = (lane & 7) + (((lane >> 3) & 1) << 3);
    const int b_col = ((lane >> 4) << 3);

    LOAD_STAGE(0, 0)

    const int NCHUNK = CIN / BK;   // 4
#pragma unroll
    for (int c = 0; c < NCHUNK; c++) {
        if (c + 1 < NCHUNK) {
            LOAD_STAGE((c + 1) & 1, (c + 1) * BK)
            asm volatile("cp.async.wait_group 1;\n" ::);
        } else {
            asm volatile("cp.async.wait_group 0;\n" ::);
        }
        __syncthreads();

        const int stg = (c & 1) * STAGE_ELEMS;
#pragma unroll
        for (int ks = 0; ks < 2; ks++) {
            const int kb = ks * 16;
            uint32_t ah[2][4], al[2][4];
#pragma unroll
            for (int mt = 0; mt < 2; mt++) {
                int ofs = stg + (kb + a_row) * 136 + wm + mt * 16 + a_col;
                ldsm4t(ah[mt], sAh + ofs);
                ldsm4t(al[mt], sAl + ofs);
            }
            uint32_t bh[8][2], bl[8][2];
#pragma unroll
            for (int jp = 0; jp < 4; jp++) {
                int ofs = stg + (kb + b_row) * 136 + wn + jp * 16 + b_col;
                uint32_t r[4];
                ldsm4t(r, sBh + ofs);
                bh[2 * jp][0] = r[0]; bh[2 * jp][1] = r[1];
                bh[2 * jp + 1][0] = r[2]; bh[2 * jp + 1][1] = r[3];
                ldsm4t(r, sBl + ofs);
                bl[2 * jp][0] = r[0]; bl[2 * jp][1] = r[1];
                bl[2 * jp + 1][0] = r[2]; bl[2 * jp + 1][1] = r[3];
            }
#pragma unroll
            for (int mt = 0; mt < 2; mt++)
#pragma unroll
                for (int j = 0; j < 8; j++) {
                    mma16816(acc[mt][j], ah[mt], bh[j]);   // hh
                    mma16816(acc[mt][j], ah[mt], bl[j]);   // hl
                    mma16816(acc[mt][j], al[mt], bh[j]);   // lh
                }
        }
        __syncthreads();
    }

    // epilogue: D frag thread L: g=L>>2, t=L&3; d0=(g,2t) d1=(g,2t+1) d2=(g+8,2t) d3=(g+8,2t+1)
    const int g = lane >> 2;
    const int t = lane & 3;
    float* out = g_cv0 + (size_t)b * 8192 * 8192;
#pragma unroll
    for (int mt = 0; mt < 2; mt++) {
        const int mrow = m0 + wm + mt * 16 + g;
#pragma unroll
        for (int j = 0; j < 8; j++) {
            const int n = n0 + wn + j * 8 + 2 * t;
            float2 v0 = make_float2(acc[mt][j][0], acc[mt][j][1]);
            float2 v1 = make_float2(acc[mt][j][2], acc[mt][j][3]);
            *(float2*)&out[(size_t)mrow * 8192 + n] = v0;
            *(float2*)&out[(size_t)(mrow + 8) * 8192 + n] = v1;
        }
    }
}

// ---------------- kernel 2: brute-force KNN ---------------------------------
template <int K>
__global__ void __launch_bounds__(128) knn_kernel(const float* __restrict__ qxyz,
                                                  const float* __restrict__ pxyz,
                                                  int Nq, int Ni, int out_off)
{
    const int CH = 1024;
    __shared__ float sx[CH], sy[CH], sz[CH];
    const int b  = blockIdx.y;
    const int qi = blockIdx.x * 128 + threadIdx.x;

    const float qx = qxyz[(size_t)(b * 3 + 0) * Nq + qi];
    const float qy = qxyz[(size_t)(b * 3 + 1) * Nq + qi];
    const float qz = qxyz[(size_t)(b * 3 + 2) * Nq + qi];
    const float qq = qx * qx + qy * qy + qz * qz;

    float bd[K];
    int   bi[K];
#pragma unroll
    for (int j = 0; j < K; j++) { bd[j] = 1e30f; bi[j] = 0; }

    for (int c0 = 0; c0 < Ni; c0 += CH) {
        const int cnt = min(CH, Ni - c0);
        for (int t = threadIdx.x; t < cnt; t += 128) {
            sx[t] = pxyz[(size_t)(b * 3 + 0) * Ni + c0 + t];
            sy[t] = pxyz[(size_t)(b * 3 + 1) * Ni + c0 + t];
            sz[t] = pxyz[(size_t)(b * 3 + 2) * Ni + c0 + t];
        }
        __syncthreads();
        for (int t = 0; t < cnt; t++) {
            const float ix = sx[t], iy = sy[t], iz = sz[t];
            const float ii = ix * ix + iy * iy + iz * iz;
            const float d  = qq + ii - 2.0f * (qx * ix + qy * iy + qz * iz);
            if (d < bd[K - 1]) {
                bd[K - 1] = d; bi[K - 1] = c0 + t;
#pragma unroll
                for (int j = K - 1; j > 0; j--) {
                    if (bd[j] < bd[j - 1]) {
                        float td = bd[j]; bd[j] = bd[j - 1]; bd[j - 1] = td;
                        int   ti = bi[j]; bi[j] = bi[j - 1]; bi[j - 1] = ti;
                    }
                }
            }
        }
        __syncthreads();
    }

    int* out = g_idx + out_off;
#pragma unroll
    for (int j = 0; j < K; j++)
        out[((size_t)b * Nq + qi) * K + j] = bi[j];
}

// ---------------- kernel 3: pyramid k=3 average -----------------------------
__global__ void __launch_bounds__(256) pyr_avg(int lvl, int Nm, int Nprev, int idx_off)
{
    const float* prev = cv_ptr(lvl - 1);
    float* out        = cv_ptr(lvl);
    const int b = blockIdx.z;
    const int m = blockIdx.y;
    const int n = blockIdx.x * 256 + threadIdx.x;
    const int* ip = g_idx + idx_off + ((size_t)b * Nm + m) * 3;
    const int i0 = ip[0], i1 = ip[1], i2 = ip[2];
    const float v = prev[((size_t)b * Nprev + i0) * 8192 + n]
                  + prev[((size_t)b * Nprev + i1) * 8192 + n]
                  + prev[((size_t)b * Nprev + i2) * 8192 + n];
    out[((size_t)b * Nm + m) * 8192 + n] = v * (1.0f / 3.0f);
}

// ---------------- kernel 4: per-level matching cost MLP ---------------------
__global__ void __launch_bounds__(128) level_cost(const float* __restrict__ xyz1,
                                                  const float* __restrict__ xyz2,
                                                  int lvl, int Nl,
                                                  const float* __restrict__ w1,
                                                  const float* __restrict__ b1,
                                                  const float* __restrict__ w2,
                                                  const float* __restrict__ b2)
{
    __shared__ float sw1[64], sb1[16], sw2[256], sb2[16];
    const int t = threadIdx.x;
    if (t < 64) sw1[t] = w1[t];
    if (t < 16) sb1[t] = b1[t];
    for (int i = t; i < 256; i += 128) sw2[i] = w2[i];
    if (t >= 64 && t < 80) sb2[t - 64] = b2[t - 64];
    __syncthreads();

    const int b = blockIdx.y;
    const int n = blockIdx.x * 128 + t;
    const float* cvT = cv_ptr(lvl);
    const int* ip = g_idx + (size_t)lvl * IDX_CROSS_STRIDE + ((size_t)b * N1 + n) * 16;

    const float px = xyz1[(size_t)(b * 3 + 0) * N1 + n];
    const float py = xyz1[(size_t)(b * 3 + 1) * N1 + n];
    const float pz = xyz1[(size_t)(b * 3 + 2) * N1 + n];

    float acc[16];
#pragma unroll
    for (int o = 0; o < 16; o++) acc[o] = 0.0f;

#pragma unroll 4
    for (int k = 0; k < 16; k++) {
        const int i = ip[k];
        const float dx = xyz2[(size_t)(b * 3 + 0) * Nl + i] - px;
        const float dy = xyz2[(size_t)(b * 3 + 1) * Nl + i] - py;
        const float dz = xyz2[(size_t)(b * 3 + 2) * Nl + i] - pz;
        const float corr = cvT[((size_t)b * Nl + i) * 8192 + n];

        float h1[16];
#pragma unroll
        for (int o = 0; o < 16; o++) {
            float a = fmaf(sw1[o * 4 + 0], dx, sb1[o]);
            a = fmaf(sw1[o * 4 + 1], dy, a);
            a = fmaf(sw1[o * 4 + 2], dz, a);
            a = fmaf(sw1[o * 4 + 3], corr, a);
            h1[o] = fmaxf(a, 0.0f);
        }
#pragma unroll
        for (int o2 = 0; o2 < 16; o2++) {
            float a = sb2[o2];
#pragma unroll
            for (int o = 0; o < 16; o++) a = fmaf(sw2[o2 * 16 + o], h1[o], a);
            acc[o2] += fmaxf(a, 0.0f);
        }
    }
#pragma unroll
    for (int o2 = 0; o2 < 16; o2++)
        g_costs[((size_t)b * 64 + lvl * 16 + o2) * N1 + n] = acc[o2];
}

// ---------------- kernel 5: final 64x64 MLP ---------------------------------
__global__ void __launch_bounds__(256) final_mlp(const float* __restrict__ wm,
                                                 const float* __restrict__ bm,
                                                 float* __restrict__ out)
{
    __shared__ float swm[4096];
    __shared__ float sbm[64];
    const int t = threadIdx.x;
    for (int i = t; i < 4096; i += 256) swm[i] = wm[i];
    if (t < 64) sbm[t] = bm[t];
    __syncthreads();

    const int b = blockIdx.y;
    const int n = blockIdx.x * 256 + t;

    float c[64];
#pragma unroll
    for (int cc = 0; cc < 64; cc++)
        c[cc] = g_costs[((size_t)b * 64 + cc) * N1 + n];

#pragma unroll 4
    for (int o = 0; o < 64; o++) {
        float a = sbm[o];
#pragma unroll
        for (int cc = 0; cc < 64; cc++)
            a = fmaf(swm[o * 64 + cc], c[cc], a);
        out[((size_t)b * 64 + o) * N1 + n] = fmaxf(a, 0.0f);
    }
}

// ---------------- launcher ---------------------------------------------------
extern "C" void kernel_launch(void* const* d_in, const int* in_sizes, int n_in,
                              void* d_out, int out_size)
{
    const float* xyz1   = (const float*)d_in[0];
    const float* xyz2_0 = (const float*)d_in[1];
    const float* xyz2_1 = (const float*)d_in[2];
    const float* xyz2_2 = (const float*)d_in[3];
    const float* xyz2_3 = (const float*)d_in[4];
    const float* feat1  = (const float*)d_in[5];
    const float* feat2  = (const float*)d_in[6];
    const float* w1 = (const float*)d_in[7];
    const float* b1 = (const float*)d_in[8];
    const float* w2 = (const float*)d_in[9];
    const float* b2 = (const float*)d_in[10];
    const float* wm = (const float*)d_in[11];
    const float* bm = (const float*)d_in[12];
    float* out = (float*)d_out;

    // 0) bf16 hi/lo split of features
    split_bf16<<<FEAT_ELEMS / 256, 256>>>(feat1, feat2);

    // 1) cost volume (transposed): cvT0[b][m][n1], via bf16-split tensor cores
    static bool smem_set = false;
    if (!smem_set) {
        cudaFuncSetAttribute(gemm_cv_mma, cudaFuncAttributeMaxDynamicSharedMemorySize,
                             8 * STAGE_ELEMS * (int)sizeof(__nv_bfloat16));
        smem_set = true;
    }
    gemm_cv_mma<<<dim3(64, 64, 2), 256, 8 * STAGE_ELEMS * sizeof(__nv_bfloat16)>>>();

    // 2) pyramid KNN (k=3)
    knn_kernel<3><<<dim3(2048 / 128, 2), 128>>>(xyz2_1, xyz2_0, 2048, 8192, IDX_PYR1);
    knn_kernel<3><<<dim3( 512 / 128, 2), 128>>>(xyz2_2, xyz2_1,  512, 2048, IDX_PYR2);
    knn_kernel<3><<<dim3( 128 / 128, 2), 128>>>(xyz2_3, xyz2_2,  128,  512, IDX_PYR3);

    // 3) cross KNN (k=16)
    knn_kernel<16><<<dim3(64, 2), 128>>>(xyz1, xyz2_0, N1, 8192, 0 * IDX_CROSS_STRIDE);
    knn_kernel<16><<<dim3(64, 2), 128>>>(xyz1, xyz2_1, N1, 2048, 1 * IDX_CROSS_STRIDE);
    knn_kernel<16><<<dim3(64, 2), 128>>>(xyz1, xyz2_2, N1,  512, 2 * IDX_CROSS_STRIDE);
    knn_kernel<16><<<dim3(64, 2), 128>>>(xyz1, xyz2_3, N1,  128, 3 * IDX_CROSS_STRIDE);

    // 4) pyramid averaging
    pyr_avg<<<dim3(32, 2048, 2), 256>>>(1, 2048, 8192, IDX_PYR1);
    pyr_avg<<<dim3(32,  512, 2), 256>>>(2,  512, 2048, IDX_PYR2);
    pyr_avg<<<dim3(32,  128, 2), 256>>>(3,  128,  512, IDX_PYR3);

    // 5) per-level matching cost MLPs
    level_cost<<<dim3(64, 2), 128>>>(xyz1, xyz2_0, 0, 8192, w1, b1, w2, b2);
    level_cost<<<dim3(64, 2), 128>>>(xyz1, xyz2_1, 1, 2048, w1, b1, w2, b2);
    level_cost<<<dim3(64, 2), 128>>>(xyz1, xyz2_2, 2,  512, w1, b1, w2, b2);
    level_cost<<<dim3(64, 2), 128>>>(xyz1, xyz2_3, 3,  128, w1, b1, w2, b2);

    // 6) final MLP -> output [2][64][8192]
    final_mlp<<<dim3(32, 2), 256>>>(wm, bm, out);
}